// round 5
// baseline (speedup 1.0000x reference)
#include <cuda_runtime.h>
#include <cuda_bf16.h>
#include <cstdint>

// Problem constants (fixed by the dataset)
#define NN 10000      // nodes
#define NE 160000     // directed edges
#define FD 512        // feature dim (IN == H == 512)
#define OUTD 16       // classes

// ----------------------------------------------------------------------------
// Scratch: __device__ globals (no runtime allocation allowed).
// ----------------------------------------------------------------------------
__device__ int   g_isI64;            // 1 if edge_index buffer is 64-bit ints
__device__ int   g_deg[NN];
__device__ int   g_cursor[NN];
__device__ float g_dinv[NN];
__device__ int   g_row_start[NN + 1];
__device__ int   g_csr_src[NE];
__device__ __align__(16) float g_bufA[(size_t)NN * FD];   // 20.48 MB (GEMM out)
__device__ __align__(16) float g_bufB[(size_t)NN * FD];   // 20.48 MB (agg out)

// ----------------------------------------------------------------------------
// Edge-index dtype detection. If the buffer is int64, the odd 32-bit words of
// the first E elements are high words of values < 2^31 -> all zero. If int32,
// they are random node ids -> OR is nonzero with overwhelming probability.
// Indices touched: 1..2*NE-1, within the minimum (int32) buffer of 2*NE words.
// ----------------------------------------------------------------------------
__global__ void detect_kernel(const int* __restrict__ ei32) {
    __shared__ int s;
    if (threadIdx.x == 0) s = 0;
    __syncthreads();
    int acc = 0;
    for (int i = threadIdx.x; i < NE; i += blockDim.x) acc |= ei32[2 * i + 1];
    if (acc) atomicOr(&s, 1);
    __syncthreads();
    if (threadIdx.x == 0) g_isI64 = (s == 0) ? 1 : 0;
}

// ----------------------------------------------------------------------------
// Graph preprocessing: degree histogram -> scan -> CSR fill
// Layout of edge_index is [2, E]: row 0 = src, row 1 = dst.
// int32 mode: src = ei32[i],     dst = ei32[NE + i]
// int64 mode: src = ei32[2*i],   dst = ei32[2*(NE + i)]   (little-endian low word)
// ----------------------------------------------------------------------------
__global__ void zero_counts_kernel() {
    int i = blockIdx.x * blockDim.x + threadIdx.x;
    if (i < NN) { g_deg[i] = 0; g_cursor[i] = 0; }
}

__global__ void count_kernel(const int* __restrict__ ei32) {
    int i = blockIdx.x * blockDim.x + threadIdx.x;
    if (i < NE) {
        int dst = g_isI64 ? ei32[2 * (NE + i)] : ei32[NE + i];
        atomicAdd(&g_deg[dst], 1);
    }
}

// Single-block exclusive scan of g_deg -> g_row_start. 1024 threads,
// 10 elements per thread (chunked), Hillis-Steele over chunk sums.
__global__ void scan_kernel() {
    __shared__ int sums[1024];
    const int CH = (NN + 1023) / 1024;   // 10
    int t = threadIdx.x;
    int start = t * CH;
    int vals[CH];
    int local = 0;
#pragma unroll
    for (int i = 0; i < CH; i++) {
        int idx = start + i;
        int v = (idx < NN) ? g_deg[idx] : 0;
        vals[i] = v;
        local += v;
    }
    sums[t] = local;
    __syncthreads();
    for (int off = 1; off < 1024; off <<= 1) {
        int v = sums[t];
        int add = (t >= off) ? sums[t - off] : 0;
        __syncthreads();
        sums[t] = v + add;
        __syncthreads();
    }
    int prefix = (t == 0) ? 0 : sums[t - 1];   // exclusive over chunks
#pragma unroll
    for (int i = 0; i < CH; i++) {
        int idx = start + i;
        if (idx < NN) { g_row_start[idx] = prefix; prefix += vals[i]; }
    }
    if (t == 1023) g_row_start[NN] = prefix;   // == NE
}

__global__ void dinv_kernel() {
    int i = blockIdx.x * blockDim.x + threadIdx.x;
    if (i < NN) g_dinv[i] = rsqrtf((float)g_deg[i] + 1.0f);
}

__global__ void fill_kernel(const int* __restrict__ ei32) {
    int i = blockIdx.x * blockDim.x + threadIdx.x;
    if (i < NE) {
        int src, dst;
        if (g_isI64) { src = ei32[2 * i]; dst = ei32[2 * (NE + i)]; }
        else         { src = ei32[i];     dst = ei32[NE + i]; }
        int pos = atomicAdd(&g_cursor[dst], 1);
        g_csr_src[g_row_start[dst] + pos] = src;
    }
}

// ----------------------------------------------------------------------------
// SGEMM: g_bufA[M x N] = A[M x K] * B[K x N], row-major, fp32.
// A = external pointer (x) when FROM_X, else g_bufB.
// 128x128 block tile, BK=8, 8x8 thread microtile, 256 threads, float4 I/O.
// ----------------------------------------------------------------------------
template <bool FROM_X>
__global__ __launch_bounds__(256)
void sgemm_kernel(const float* __restrict__ Aext, const float* __restrict__ B,
                  int M, int N, int K) {
    constexpr int BM = 128, BN = 128, BK = 8, TM = 8, TN = 8;
    __shared__ __align__(16) float As[BK][BM];   // transposed A tile
    __shared__ __align__(16) float Bs[BK][BN];

    const float* A = FROM_X ? Aext : (const float*)g_bufB;
    float* C = (float*)g_bufA;

    int tid = threadIdx.x;
    int blockRow = blockIdx.y * BM;
    int blockCol = blockIdx.x * BN;

    int tRow = (tid / (BN / TN)) * TM;   // 0..120 step 8
    int tCol = (tid % (BN / TN)) * TN;   // 0..120 step 8

    // A tile load map: 128 rows x 8 cols = 256 float4
    int aRow = tid >> 1;            // 0..127
    int aCol = (tid & 1) * 4;       // 0 or 4
    // B tile load map: 8 rows x 128 cols = 256 float4
    int bRow = tid >> 5;            // 0..7
    int bCol = (tid & 31) * 4;      // 0..124

    float acc[TM][TN];
#pragma unroll
    for (int i = 0; i < TM; i++)
#pragma unroll
        for (int j = 0; j < TN; j++) acc[i][j] = 0.0f;

    int gRow = blockRow + aRow;
    bool aValid = (gRow < M);
    const float* aSrc = A + (size_t)(aValid ? gRow : 0) * K + aCol;
    const float* bSrc = B + (size_t)bRow * N + blockCol + bCol;

    for (int k0 = 0; k0 < K; k0 += BK) {
        float4 a4 = make_float4(0.f, 0.f, 0.f, 0.f);
        if (aValid) a4 = *(const float4*)(aSrc + k0);
        As[aCol + 0][aRow] = a4.x;
        As[aCol + 1][aRow] = a4.y;
        As[aCol + 2][aRow] = a4.z;
        As[aCol + 3][aRow] = a4.w;
        float4 b4 = *(const float4*)(bSrc + (size_t)k0 * N);
        *(float4*)&Bs[bRow][bCol] = b4;
        __syncthreads();

#pragma unroll
        for (int k = 0; k < BK; k++) {
            float4 m0 = *(const float4*)&As[k][tRow];
            float4 m1 = *(const float4*)&As[k][tRow + 4];
            float4 n0 = *(const float4*)&Bs[k][tCol];
            float4 n1 = *(const float4*)&Bs[k][tCol + 4];
            float regM[TM] = {m0.x, m0.y, m0.z, m0.w, m1.x, m1.y, m1.z, m1.w};
            float regN[TN] = {n0.x, n0.y, n0.z, n0.w, n1.x, n1.y, n1.z, n1.w};
#pragma unroll
            for (int i = 0; i < TM; i++)
#pragma unroll
                for (int j = 0; j < TN; j++)
                    acc[i][j] += regM[i] * regN[j];
        }
        __syncthreads();
    }

#pragma unroll
    for (int i = 0; i < TM; i++) {
        int gr = blockRow + tRow + i;
        if (gr < M) {
            float* cp = C + (size_t)gr * N + blockCol + tCol;
            *(float4*)(cp)     = make_float4(acc[i][0], acc[i][1], acc[i][2], acc[i][3]);
            *(float4*)(cp + 4) = make_float4(acc[i][4], acc[i][5], acc[i][6], acc[i][7]);
        }
    }
}

// ----------------------------------------------------------------------------
// Aggregation: g_bufB[dst] = sum_{e in CSR(dst)} dinv[src]*dinv[dst]*g_bufA[src]
//                          + dinv[dst]^2 * g_bufA[dst] + bias, ReLU.
// One 128-thread block per destination node, float4 per thread (512 feats).
// Pure gather from L2-resident g_bufA; no float atomics.
// ----------------------------------------------------------------------------
__global__ __launch_bounds__(128)
void agg_kernel(const float* __restrict__ bias) {
    const float* h = (const float*)g_bufA;
    float* out = (float*)g_bufB;
    int node = blockIdx.x;
    int t = threadIdx.x;
    __shared__ int   s_src[128];
    __shared__ float s_w[128];

    float dd = g_dinv[node];
    float4 acc;
    {
        float4 v = *(const float4*)(h + (size_t)node * FD + t * 4);
        float w = dd * dd;
        acc = make_float4(v.x * w, v.y * w, v.z * w, v.w * w);
    }

    int beg = g_row_start[node];
    int end = g_row_start[node + 1];
    for (int c = beg; c < end; c += 128) {
        int n = min(end - c, 128);
        if (t < n) {
            int s = g_csr_src[c + t];
            s_src[t] = s;
            s_w[t] = g_dinv[s] * dd;
        }
        __syncthreads();
        for (int e = 0; e < n; e++) {
            int s = s_src[e];
            float w = s_w[e];
            float4 v = *(const float4*)(h + (size_t)s * FD + t * 4);
            acc.x += w * v.x; acc.y += w * v.y;
            acc.z += w * v.z; acc.w += w * v.w;
        }
        __syncthreads();
    }

    float4 b = *(const float4*)(bias + t * 4);
    acc.x = fmaxf(acc.x + b.x, 0.f);
    acc.y = fmaxf(acc.y + b.y, 0.f);
    acc.z = fmaxf(acc.z + b.z, 0.f);
    acc.w = fmaxf(acc.w + b.w, 0.f);
    *(float4*)(out + (size_t)node * FD + t * 4) = acc;
}

// ----------------------------------------------------------------------------
// Final linear: out[N x 16] = g_bufB[N x 512] @ Wl[512 x 16] + bl
// 256 threads per block, 16 rows per block; Wl staged in smem.
// ----------------------------------------------------------------------------
__global__ __launch_bounds__(256)
void linear16_kernel(const float* __restrict__ W, const float* __restrict__ b,
                     float* __restrict__ out) {
    const float* h = (const float*)g_bufB;
    __shared__ float sW[FD * OUTD];   // 32 KB
    int t = threadIdx.x;
    for (int i = t; i < FD * OUTD; i += 256) sW[i] = W[i];
    __syncthreads();

    int r = t >> 4;
    int c = t & 15;
    int row = blockIdx.x * 16 + r;
    if (row >= NN) return;

    const float4* hp = (const float4*)(h + (size_t)row * FD);
    float acc = 0.f;
#pragma unroll 4
    for (int k = 0; k < FD / 4; k++) {
        float4 v = hp[k];
        acc += v.x * sW[(4 * k + 0) * OUTD + c];
        acc += v.y * sW[(4 * k + 1) * OUTD + c];
        acc += v.z * sW[(4 * k + 2) * OUTD + c];
        acc += v.w * sW[(4 * k + 3) * OUTD + c];
    }
    out[(size_t)row * OUTD + c] = acc + b[c];
}

// ----------------------------------------------------------------------------
// Launch: x, edge_index([2,E] int32 or int64), W1, b1, W2, b2, Wl, bl
//         -> out [N,16] f32
// ----------------------------------------------------------------------------
extern "C" void kernel_launch(void* const* d_in, const int* in_sizes, int n_in,
                              void* d_out, int out_size) {
    const float* x  = (const float*)d_in[0];
    const int*   ei = (const int*)d_in[1];     // raw words; dtype detected on device
    const float* W1 = (const float*)d_in[2];
    const float* b1 = (const float*)d_in[3];
    const float* W2 = (const float*)d_in[4];
    const float* b2 = (const float*)d_in[5];
    const float* Wl = (const float*)d_in[6];
    const float* bl = (const float*)d_in[7];
    float* out = (float*)d_out;

    // Graph preprocessing (CSR by destination)
    detect_kernel<<<1, 1024>>>(ei);
    zero_counts_kernel<<<(NN + 255) / 256, 256>>>();
    count_kernel<<<(NE + 255) / 256, 256>>>(ei);
    scan_kernel<<<1, 1024>>>();
    dinv_kernel<<<(NN + 255) / 256, 256>>>();
    fill_kernel<<<(NE + 255) / 256, 256>>>(ei);

    dim3 gemmGrid(FD / 128, (NN + 127) / 128);   // (4, 79)

    // Layer 1: bufA = x @ W1 ; bufB = relu(agg(bufA) + b1)
    sgemm_kernel<true><<<gemmGrid, 256>>>(x, W1, NN, FD, FD);
    agg_kernel<<<NN, 128>>>(b1);

    // Layer 2: bufA = bufB @ W2 ; bufB = relu(agg(bufA) + b2)
    sgemm_kernel<false><<<gemmGrid, 256>>>(nullptr, W2, NN, FD, FD);
    agg_kernel<<<NN, 128>>>(b2);

    // Head: out = bufB @ Wl + bl
    linear16_kernel<<<(NN + 15) / 16, 256>>>(Wl, bl, out);
}

// round 7
// speedup vs baseline: 1.8637x; 1.8637x over previous
#include <cuda_runtime.h>
#include <cuda_bf16.h>
#include <cstdint>

// Problem constants (fixed by the dataset)
#define NN 10000      // nodes
#define NE 160000     // directed edges
#define FD 512        // feature dim (IN == H == 512)
#define OUTD 16       // classes
#define M_PAD 10112   // 79 * 128 (padded M for GEMM tiles)

// ----------------------------------------------------------------------------
// Scratch: __device__ globals (no runtime allocation allowed).
// ----------------------------------------------------------------------------
__device__ int   g_isI64;
__device__ int   g_deg[NN];
__device__ int   g_cursor[NN];
__device__ float g_dinv[NN];
__device__ int   g_row_start[NN + 1];
__device__ int   g_csr_src[NE];
__device__ __align__(16) float g_bufA[(size_t)NN * FD];   // GEMM out (fp32)
__device__ __align__(16) float g_bufB[(size_t)NN * FD];   // agg out (fp32)
__device__ __align__(16) __nv_bfloat16 g_Ahi[(size_t)M_PAD * FD];
__device__ __align__(16) __nv_bfloat16 g_Alo[(size_t)M_PAD * FD];
__device__ __align__(16) __nv_bfloat16 g_Whi[FD * FD];    // transposed [N][K]
__device__ __align__(16) __nv_bfloat16 g_Wlo[FD * FD];    // transposed [N][K]

// SW128 swizzle on byte offsets (XOR bits[6:4] with bits[9:7])
#define SWZ(o) ((o) ^ (((o) >> 3) & 0x70))

__device__ __forceinline__ uint32_t smem_u32(const void* p) {
    uint32_t a;
    asm("{ .reg .u64 t; cvta.to.shared.u64 t, %1; cvt.u32.u64 %0, t; }"
        : "=r"(a) : "l"(p));
    return a;
}

__device__ __forceinline__ void ldmx4(uint32_t addr, uint32_t* r) {
    asm volatile("ldmatrix.sync.aligned.m8n8.x4.shared.b16 {%0,%1,%2,%3}, [%4];"
                 : "=r"(r[0]), "=r"(r[1]), "=r"(r[2]), "=r"(r[3]) : "r"(addr));
}
__device__ __forceinline__ void mma_bf16(float* c, const uint32_t* a,
                                         const uint32_t* b) {
    asm volatile(
        "mma.sync.aligned.m16n8k16.row.col.f32.bf16.bf16.f32 "
        "{%0,%1,%2,%3},{%4,%5,%6,%7},{%8,%9},{%0,%1,%2,%3};"
        : "+f"(c[0]), "+f"(c[1]), "+f"(c[2]), "+f"(c[3])
        : "r"(a[0]), "r"(a[1]), "r"(a[2]), "r"(a[3]), "r"(b[0]), "r"(b[1]));
}

// ----------------------------------------------------------------------------
// Edge-index dtype detection (as R5)
// ----------------------------------------------------------------------------
__global__ void detect_kernel(const int* __restrict__ ei32) {
    __shared__ int s;
    if (threadIdx.x == 0) s = 0;
    __syncthreads();
    int acc = 0;
    for (int i = threadIdx.x; i < NE; i += blockDim.x) acc |= ei32[2 * i + 1];
    if (acc) atomicOr(&s, 1);
    __syncthreads();
    if (threadIdx.x == 0) g_isI64 = (s == 0) ? 1 : 0;
}

__global__ void zero_counts_kernel() {
    int i = blockIdx.x * blockDim.x + threadIdx.x;
    if (i < NN) { g_deg[i] = 0; g_cursor[i] = 0; }
}

__global__ void count_kernel(const int* __restrict__ ei32) {
    int i = blockIdx.x * blockDim.x + threadIdx.x;
    if (i < NE) {
        int dst = g_isI64 ? ei32[2 * (NE + i)] : ei32[NE + i];
        atomicAdd(&g_deg[dst], 1);
    }
}

// Single-block exclusive scan of g_deg -> g_row_start; also emits g_dinv.
__global__ void scan_kernel() {
    __shared__ int sums[1024];
    const int CH = (NN + 1023) / 1024;   // 10
    int t = threadIdx.x;
    int start = t * CH;
    int vals[CH];
    int local = 0;
#pragma unroll
    for (int i = 0; i < CH; i++) {
        int idx = start + i;
        int v = (idx < NN) ? g_deg[idx] : 0;
        if (idx < NN) g_dinv[idx] = rsqrtf((float)v + 1.0f);
        vals[i] = v;
        local += v;
    }
    sums[t] = local;
    __syncthreads();
    for (int off = 1; off < 1024; off <<= 1) {
        int v = sums[t];
        int add = (t >= off) ? sums[t - off] : 0;
        __syncthreads();
        sums[t] = v + add;
        __syncthreads();
    }
    int prefix = (t == 0) ? 0 : sums[t - 1];
#pragma unroll
    for (int i = 0; i < CH; i++) {
        int idx = start + i;
        if (idx < NN) { g_row_start[idx] = prefix; prefix += vals[i]; }
    }
    if (t == 1023) g_row_start[NN] = prefix;
}

__global__ void fill_kernel(const int* __restrict__ ei32) {
    int i = blockIdx.x * blockDim.x + threadIdx.x;
    if (i < NE) {
        int src, dst;
        if (g_isI64) { src = ei32[2 * i]; dst = ei32[2 * (NE + i)]; }
        else         { src = ei32[i];     dst = ei32[NE + i]; }
        int pos = atomicAdd(&g_cursor[dst], 1);
        g_csr_src[g_row_start[dst] + pos] = src;
    }
}

// ----------------------------------------------------------------------------
// fp32 -> bf16 hi/lo split conversions
// ----------------------------------------------------------------------------
__device__ __forceinline__ uint32_t pk2(__nv_bfloat16 a, __nv_bfloat16 b) {
    __nv_bfloat162 t(a, b);
    return *reinterpret_cast<uint32_t*>(&t);
}

// A (activations): src [NN, FD] fp32 -> g_Ahi/g_Alo [M_PAD, FD], zero padding.
template <bool FROM_X>
__global__ __launch_bounds__(256)
void conva_kernel(const float* __restrict__ xext) {
    size_t i = ((size_t)blockIdx.x * blockDim.x + threadIdx.x) * 4;
    if (i >= (size_t)M_PAD * FD) return;
    int row = (int)(i >> 9);
    float4 v = make_float4(0.f, 0.f, 0.f, 0.f);
    if (row < NN) {
        const float* src = FROM_X ? xext : (const float*)g_bufB;
        v = *(const float4*)(src + i);
    }
    __nv_bfloat16 h0 = __float2bfloat16(v.x), h1 = __float2bfloat16(v.y);
    __nv_bfloat16 h2 = __float2bfloat16(v.z), h3 = __float2bfloat16(v.w);
    __nv_bfloat16 l0 = __float2bfloat16(v.x - __bfloat162float(h0));
    __nv_bfloat16 l1 = __float2bfloat16(v.y - __bfloat162float(h1));
    __nv_bfloat16 l2 = __float2bfloat16(v.z - __bfloat162float(h2));
    __nv_bfloat16 l3 = __float2bfloat16(v.w - __bfloat162float(h3));
    *(uint2*)(g_Ahi + i) = make_uint2(pk2(h0, h1), pk2(h2, h3));
    *(uint2*)(g_Alo + i) = make_uint2(pk2(l0, l1), pk2(l2, l3));
}

// W [K=512, N=512] fp32 -> g_Whi/g_Wlo transposed to [N, K] bf16.
__global__ __launch_bounds__(256)
void convw_kernel(const float* __restrict__ W) {
    int i = blockIdx.x * blockDim.x + threadIdx.x;   // output index n*512 + k
    if (i < FD * FD) {
        int n = i >> 9, k = i & (FD - 1);
        float v = W[(size_t)k * FD + n];
        __nv_bfloat16 hi = __float2bfloat16(v);
        g_Whi[i] = hi;
        g_Wlo[i] = __float2bfloat16(v - __bfloat162float(hi));
    }
}

// ----------------------------------------------------------------------------
// Split-precision bf16 GEMM via mma.sync (HMMA; no tcgen05 on this target):
//   g_bufA[M_PAD x 512] = Ahi@Whi^T + Ahi@Wlo^T + Alo@Whi^T   (fp32 accum)
// CTA 128x128, 8 warps (warp tile 64x32), BK=64. SW128-swizzled smem tiles,
// conflict-free ldmatrix. 64KB smem, 2 CTAs/SM for load/math overlap.
// ----------------------------------------------------------------------------
#define GEMM_SMEM (4 * 16384)

__global__ __launch_bounds__(256, 2)
void gemm_mma_kernel() {
    extern __shared__ __align__(1024) char smem[];
    const int OFF_AHI = 0;
    const int OFF_ALO = 16384;
    const int OFF_BHI = 32768;
    const int OFF_BLO = 49152;

    const int tid = threadIdx.x;
    const int wid = tid >> 5;
    const int lane = tid & 31;
    const int warp_m = (wid & 1) * 64;   // 0 or 64
    const int warp_n = (wid >> 1) * 32;  // 0,32,64,96
    const int blockCol = blockIdx.x * 128;
    const int blockRow = blockIdx.y * 128;

    const uint32_t sb = smem_u32(smem);

    float acc[4][4][4];
#pragma unroll
    for (int i = 0; i < 4; i++)
#pragma unroll
        for (int j = 0; j < 4; j++)
#pragma unroll
            for (int k = 0; k < 4; k++) acc[i][j][k] = 0.f;

    // ldmatrix per-lane row/byte offsets (within a tile, before swizzle)
    // A (x4, m16 x k16): rows m0..15 via (lane&15), k half via (lane>>4)
    const int aRowL = (lane & 15);
    const int aKbL  = (lane >> 4) * 16;
    // B (x4, two n8 tiles x k16): row = nBase + ((lane>>4)<<3) + (lane&7),
    //                             k half via bit3
    const int bRowL = ((lane >> 4) << 3) + (lane & 7);
    const int bKbL  = ((lane >> 3) & 1) * 16;

    for (int kc = 0; kc < FD / 64; kc++) {
        // Cooperative load: 4 tiles of 128 rows x 64 bf16 (128B rows, SW128)
#pragma unroll
        for (int t = 0; t < 4; t++) {
            int l = tid + t * 256;            // 0..1023
            int row = l >> 3, seg = l & 7;
            int sw = SWZ(row * 128 + seg * 16);
            size_t aidx = (size_t)(blockRow + row) * FD + kc * 64 + seg * 8;
            size_t bidx = (size_t)(blockCol + row) * FD + kc * 64 + seg * 8;
            *(uint4*)(smem + OFF_AHI + sw) = *(const uint4*)(g_Ahi + aidx);
            *(uint4*)(smem + OFF_ALO + sw) = *(const uint4*)(g_Alo + aidx);
            *(uint4*)(smem + OFF_BHI + sw) = *(const uint4*)(g_Whi + bidx);
            *(uint4*)(smem + OFF_BLO + sw) = *(const uint4*)(g_Wlo + bidx);
        }
        __syncthreads();

#pragma unroll
        for (int s = 0; s < 4; s++) {        // k16 steps within the 64-chunk
            // B fragments: 4 n-tiles (8 cols each) -> 2 ldmatrix.x4 per matrix
            uint32_t bh[8], bl[8];
#pragma unroll
            for (int p = 0; p < 2; p++) {
                int brow = warp_n + p * 16 + bRowL;
                int boff = SWZ(brow * 128 + s * 32 + bKbL);
                ldmx4(sb + OFF_BHI + boff, &bh[p * 4]);
                ldmx4(sb + OFF_BLO + boff, &bl[p * 4]);
            }
#pragma unroll
            for (int mt = 0; mt < 4; mt++) {
                int arow = warp_m + mt * 16 + aRowL;
                int aoff = SWZ(arow * 128 + s * 32 + aKbL);
                uint32_t ah[4], al[4];
                ldmx4(sb + OFF_AHI + aoff, ah);
                ldmx4(sb + OFF_ALO + aoff, al);
#pragma unroll
                for (int nt = 0; nt < 4; nt++) {
                    mma_bf16(acc[mt][nt], ah, &bh[nt * 2]);
                    mma_bf16(acc[mt][nt], ah, &bl[nt * 2]);
                    mma_bf16(acc[mt][nt], al, &bh[nt * 2]);
                }
            }
        }
        __syncthreads();
    }

    // Epilogue: c0,c1 -> (m, n..n+1); c2,c3 -> (m+8, n..n+1)
    const int mBase = blockRow + warp_m + (lane >> 2);
    const int nBase = blockCol + warp_n + (lane & 3) * 2;
#pragma unroll
    for (int mt = 0; mt < 4; mt++) {
        int m0 = mBase + mt * 16;
#pragma unroll
        for (int nt = 0; nt < 4; nt++) {
            int n = nBase + nt * 8;
            if (m0 < NN)
                *(float2*)(g_bufA + (size_t)m0 * FD + n) =
                    make_float2(acc[mt][nt][0], acc[mt][nt][1]);
            if (m0 + 8 < NN)
                *(float2*)(g_bufA + (size_t)(m0 + 8) * FD + n) =
                    make_float2(acc[mt][nt][2], acc[mt][nt][3]);
        }
    }
}

// ----------------------------------------------------------------------------
// Aggregation (as R5): g_bufB[dst] = sum norm*g_bufA[src] + self + bias, ReLU
// ----------------------------------------------------------------------------
__global__ __launch_bounds__(128)
void agg_kernel(const float* __restrict__ bias) {
    const float* h = (const float*)g_bufA;
    float* out = (float*)g_bufB;
    int node = blockIdx.x;
    int t = threadIdx.x;
    __shared__ int   s_src[128];
    __shared__ float s_w[128];

    float dd = g_dinv[node];
    float4 acc;
    {
        float4 v = *(const float4*)(h + (size_t)node * FD + t * 4);
        float w = dd * dd;
        acc = make_float4(v.x * w, v.y * w, v.z * w, v.w * w);
    }

    int beg = g_row_start[node];
    int end = g_row_start[node + 1];
    for (int c = beg; c < end; c += 128) {
        int n = min(end - c, 128);
        if (t < n) {
            int s = g_csr_src[c + t];
            s_src[t] = s;
            s_w[t] = g_dinv[s] * dd;
        }
        __syncthreads();
        for (int e = 0; e < n; e++) {
            int s = s_src[e];
            float w = s_w[e];
            float4 v = *(const float4*)(h + (size_t)s * FD + t * 4);
            acc.x += w * v.x; acc.y += w * v.y;
            acc.z += w * v.z; acc.w += w * v.w;
        }
        __syncthreads();
    }

    float4 b = *(const float4*)(bias + t * 4);
    acc.x = fmaxf(acc.x + b.x, 0.f);
    acc.y = fmaxf(acc.y + b.y, 0.f);
    acc.z = fmaxf(acc.z + b.z, 0.f);
    acc.w = fmaxf(acc.w + b.w, 0.f);
    *(float4*)(out + (size_t)node * FD + t * 4) = acc;
}

// ----------------------------------------------------------------------------
// Final linear (as R5): out[N x 16] = g_bufB @ Wl + bl
// ----------------------------------------------------------------------------
__global__ __launch_bounds__(256)
void linear16_kernel(const float* __restrict__ W, const float* __restrict__ b,
                     float* __restrict__ out) {
    const float* h = (const float*)g_bufB;
    __shared__ float sW[FD * OUTD];
    int t = threadIdx.x;
    for (int i = t; i < FD * OUTD; i += 256) sW[i] = W[i];
    __syncthreads();

    int r = t >> 4;
    int c = t & 15;
    int row = blockIdx.x * 16 + r;
    if (row >= NN) return;

    const float4* hp = (const float4*)(h + (size_t)row * FD);
    float acc = 0.f;
#pragma unroll 4
    for (int k = 0; k < FD / 4; k++) {
        float4 v = hp[k];
        acc += v.x * sW[(4 * k + 0) * OUTD + c];
        acc += v.y * sW[(4 * k + 1) * OUTD + c];
        acc += v.z * sW[(4 * k + 2) * OUTD + c];
        acc += v.w * sW[(4 * k + 3) * OUTD + c];
    }
    out[(size_t)row * OUTD + c] = acc + b[c];
}

// ----------------------------------------------------------------------------
// Launch
// ----------------------------------------------------------------------------
extern "C" void kernel_launch(void* const* d_in, const int* in_sizes, int n_in,
                              void* d_out, int out_size) {
    const float* x  = (const float*)d_in[0];
    const int*   ei = (const int*)d_in[1];
    const float* W1 = (const float*)d_in[2];
    const float* b1 = (const float*)d_in[3];
    const float* W2 = (const float*)d_in[4];
    const float* b2 = (const float*)d_in[5];
    const float* Wl = (const float*)d_in[6];
    const float* bl = (const float*)d_in[7];
    float* out = (float*)d_out;

    // 64KB dynamic smem opt-in (attribute set is not a stream op; capture-safe)
    cudaFuncSetAttribute(gemm_mma_kernel,
                         cudaFuncAttributeMaxDynamicSharedMemorySize, GEMM_SMEM);

    // Graph preprocessing (CSR by destination)
    detect_kernel<<<1, 1024>>>(ei);
    zero_counts_kernel<<<(NN + 255) / 256, 256>>>();
    count_kernel<<<(NE + 255) / 256, 256>>>(ei);
    scan_kernel<<<1, 1024>>>();
    fill_kernel<<<(NE + 255) / 256, 256>>>(ei);

    dim3 gemmGrid(FD / 128, M_PAD / 128);                 // (4, 79)
    int convaBlocks = (int)(((size_t)M_PAD * FD / 4 + 255) / 256);

    // Layer 1
    convw_kernel<<<(FD * FD + 255) / 256, 256>>>(W1);
    conva_kernel<true><<<convaBlocks, 256>>>(x);
    gemm_mma_kernel<<<gemmGrid, 256, GEMM_SMEM>>>();
    agg_kernel<<<NN, 128>>>(b1);

    // Layer 2
    convw_kernel<<<(FD * FD + 255) / 256, 256>>>(W2);
    conva_kernel<false><<<convaBlocks, 256>>>(nullptr);
    gemm_mma_kernel<<<gemmGrid, 256, GEMM_SMEM>>>();
    agg_kernel<<<NN, 128>>>(b2);

    // Head
    linear16_kernel<<<(NN + 15) / 16, 256>>>(Wl, bl, out);
}

// round 8
// speedup vs baseline: 2.2264x; 1.1946x over previous
#include <cuda_runtime.h>
#include <cuda_bf16.h>
#include <cstdint>

// Problem constants (fixed by the dataset)
#define NN 10000      // nodes
#define NE 160000     // directed edges
#define FD 512        // feature dim (IN == H == 512)
#define OUTD 16       // classes
#define M_PAD 10112   // 79 * 128 (padded M for GEMM tiles)

// ----------------------------------------------------------------------------
// Scratch: __device__ globals (no runtime allocation allowed).
// ----------------------------------------------------------------------------
__device__ int   g_deg[NN];
__device__ int   g_cursor[NN];
__device__ float g_dinv[NN];
__device__ int   g_row_start[NN + 1];
__device__ int   g_csr_src[NE];
__device__ __align__(16) float g_bufA[(size_t)NN * FD];   // GEMM out (fp32)
__device__ __align__(16) float g_bufB[(size_t)NN * FD];   // agg2 out (fp32)
__device__ __align__(16) __nv_bfloat16 g_Ahi[(size_t)M_PAD * FD];
__device__ __align__(16) __nv_bfloat16 g_Alo[(size_t)M_PAD * FD];
__device__ __align__(16) __nv_bfloat16 g_Whi[2][FD * FD]; // transposed [N][K]
__device__ __align__(16) __nv_bfloat16 g_Wlo[2][FD * FD]; // transposed [N][K]

// SW64 swizzle on byte offsets (64B rows): XOR bits[5:4] with bits[8:7]
#define SWZ64(o) ((o) ^ (((o) >> 3) & 0x30))

__device__ __forceinline__ uint32_t smem_u32(const void* p) {
    uint32_t a;
    asm("{ .reg .u64 t; cvta.to.shared.u64 t, %1; cvt.u32.u64 %0, t; }"
        : "=r"(a) : "l"(p));
    return a;
}
__device__ __forceinline__ void ldmx4(uint32_t addr, uint32_t* r) {
    asm volatile("ldmatrix.sync.aligned.m8n8.x4.shared.b16 {%0,%1,%2,%3}, [%4];"
                 : "=r"(r[0]), "=r"(r[1]), "=r"(r[2]), "=r"(r[3]) : "r"(addr));
}
__device__ __forceinline__ void mma_bf16(float* c, const uint32_t* a,
                                         const uint32_t* b) {
    asm volatile(
        "mma.sync.aligned.m16n8k16.row.col.f32.bf16.bf16.f32 "
        "{%0,%1,%2,%3},{%4,%5,%6,%7},{%8,%9},{%0,%1,%2,%3};"
        : "+f"(c[0]), "+f"(c[1]), "+f"(c[2]), "+f"(c[3])
        : "r"(a[0]), "r"(a[1]), "r"(a[2]), "r"(a[3]), "r"(b[0]), "r"(b[1]));
}
__device__ __forceinline__ void cpasync16(uint32_t s, const void* g) {
    asm volatile("cp.async.cg.shared.global [%0], [%1], 16;" :: "r"(s), "l"(g));
}
#define CP_COMMIT() asm volatile("cp.async.commit_group;")

// Per-block edge_index dtype detection: if buffer is int64, odd words of the
// first 32 elements are high words of values < 2^31 -> all zero.
__device__ __forceinline__ int detect_i64(const int* __restrict__ ei32) {
    int o = 0;
#pragma unroll
    for (int j = 0; j < 32; j++) o |= ei32[2 * j + 1];
    return (o == 0) ? 1 : 0;
}

// ----------------------------------------------------------------------------
// Graph preprocessing
// ----------------------------------------------------------------------------
__global__ void zero_counts_kernel() {
    int i = blockIdx.x * blockDim.x + threadIdx.x;
    if (i < NN) { g_deg[i] = 0; g_cursor[i] = 0; }
}

__global__ void count_kernel(const int* __restrict__ ei32) {
    __shared__ int s_i64;
    if (threadIdx.x == 0) s_i64 = detect_i64(ei32);
    __syncthreads();
    int i = blockIdx.x * blockDim.x + threadIdx.x;
    if (i < NE) {
        int dst = s_i64 ? ei32[2 * (NE + i)] : ei32[NE + i];
        atomicAdd(&g_deg[dst], 1);
    }
}

// Single-block exclusive scan of g_deg -> g_row_start (no MUFU work here).
__global__ void scan_kernel() {
    __shared__ int sums[1024];
    const int CH = (NN + 1023) / 1024;   // 10
    int t = threadIdx.x;
    int start = t * CH;
    int vals[CH];
    int local = 0;
#pragma unroll
    for (int i = 0; i < CH; i++) {
        int idx = start + i;
        int v = (idx < NN) ? g_deg[idx] : 0;
        vals[i] = v;
        local += v;
    }
    sums[t] = local;
    __syncthreads();
    for (int off = 1; off < 1024; off <<= 1) {
        int v = sums[t];
        int add = (t >= off) ? sums[t - off] : 0;
        __syncthreads();
        sums[t] = v + add;
        __syncthreads();
    }
    int prefix = (t == 0) ? 0 : sums[t - 1];
#pragma unroll
    for (int i = 0; i < CH; i++) {
        int idx = start + i;
        if (idx < NN) { g_row_start[idx] = prefix; prefix += vals[i]; }
    }
    if (t == 1023) g_row_start[NN] = prefix;
}

// CSR fill + grid-wide dinv (rsqrt spread over the whole chip, not one SM).
__global__ void fill_kernel(const int* __restrict__ ei32) {
    __shared__ int s_i64;
    if (threadIdx.x == 0) s_i64 = detect_i64(ei32);
    __syncthreads();
    int i = blockIdx.x * blockDim.x + threadIdx.x;
    if (i < NE) {
        int src, dst;
        if (s_i64) { src = ei32[2 * i]; dst = ei32[2 * (NE + i)]; }
        else       { src = ei32[i];     dst = ei32[NE + i]; }
        int pos = atomicAdd(&g_cursor[dst], 1);
        g_csr_src[g_row_start[dst] + pos] = src;
    }
    for (int n = i; n < NN; n += gridDim.x * blockDim.x)
        g_dinv[n] = rsqrtf((float)g_deg[n] + 1.0f);
}

// ----------------------------------------------------------------------------
// fp32 -> bf16 hi/lo split conversions
// ----------------------------------------------------------------------------
__device__ __forceinline__ uint32_t pk2(__nv_bfloat16 a, __nv_bfloat16 b) {
    __nv_bfloat162 t(a, b);
    return *reinterpret_cast<uint32_t*>(&t);
}
__device__ __forceinline__ void split4(float4 v, uint2& hi, uint2& lo) {
    __nv_bfloat16 h0 = __float2bfloat16(v.x), h1 = __float2bfloat16(v.y);
    __nv_bfloat16 h2 = __float2bfloat16(v.z), h3 = __float2bfloat16(v.w);
    __nv_bfloat16 l0 = __float2bfloat16(v.x - __bfloat162float(h0));
    __nv_bfloat16 l1 = __float2bfloat16(v.y - __bfloat162float(h1));
    __nv_bfloat16 l2 = __float2bfloat16(v.z - __bfloat162float(h2));
    __nv_bfloat16 l3 = __float2bfloat16(v.w - __bfloat162float(h3));
    hi = make_uint2(pk2(h0, h1), pk2(h2, h3));
    lo = make_uint2(pk2(l0, l1), pk2(l2, l3));
}

// x [NN, FD] fp32 -> g_Ahi/g_Alo [M_PAD, FD], zero padding rows.
__global__ __launch_bounds__(256)
void conva_kernel(const float* __restrict__ x) {
    size_t i = ((size_t)blockIdx.x * blockDim.x + threadIdx.x) * 4;
    if (i >= (size_t)M_PAD * FD) return;
    int row = (int)(i >> 9);
    float4 v = make_float4(0.f, 0.f, 0.f, 0.f);
    if (row < NN) v = *(const float4*)(x + i);
    uint2 hi, lo;
    split4(v, hi, lo);
    *(uint2*)(g_Ahi + i) = hi;
    *(uint2*)(g_Alo + i) = lo;
}

// Both W [K,N] fp32 -> g_Whi/g_Wlo[layer] transposed to [N,K] bf16.
__global__ __launch_bounds__(256)
void convw_kernel(const float* __restrict__ W1, const float* __restrict__ W2) {
    int i = blockIdx.x * blockDim.x + threadIdx.x;
    if (i < 2 * FD * FD) {
        int layer = i >> 18;                    // / (FD*FD)
        int r = i & (FD * FD - 1);
        int n = r >> 9, k = r & (FD - 1);
        const float* W = layer ? W2 : W1;
        float v = W[(size_t)k * FD + n];
        __nv_bfloat16 hi = __float2bfloat16(v);
        g_Whi[layer][r] = hi;
        g_Wlo[layer][r] = __float2bfloat16(v - __bfloat162float(hi));
    }
}

// ----------------------------------------------------------------------------
// Split-precision bf16 GEMM via mma.sync, cp.async 2-stage pipeline:
//   g_bufA[M_PAD x 512] = Ahi@Whi^T + Ahi@Wlo^T + Alo@Whi^T   (fp32 accum)
// CTA 128x128, 8 warps (warp tile 64x32), BK=32, SW64-swizzled 64B rows.
// Stage = 32KB (Ahi/Alo/Bhi/Blo 8KB each); 2 stages = 64KB; 2 CTAs/SM.
// ----------------------------------------------------------------------------
#define STAGE_BYTES 32768
#define GEMM_SMEM   (2 * STAGE_BYTES)

template <int LAYER>
__global__ __launch_bounds__(256, 2)
void gemm_mma_kernel() {
    extern __shared__ __align__(1024) char smem[];
    const uint32_t sb = smem_u32(smem);

    const int tid = threadIdx.x;
    const int wid = tid >> 5;
    const int lane = tid & 31;
    const int warp_m = (wid & 1) * 64;
    const int warp_n = (wid >> 1) * 32;
    const int blockCol = blockIdx.x * 128;
    const int blockRow = blockIdx.y * 128;

    const __nv_bfloat16* Wh = g_Whi[LAYER];
    const __nv_bfloat16* Wl = g_Wlo[LAYER];

    float acc[4][4][4];
#pragma unroll
    for (int i = 0; i < 4; i++)
#pragma unroll
        for (int j = 0; j < 4; j++)
#pragma unroll
            for (int k = 0; k < 4; k++) acc[i][j][k] = 0.f;

    const int aRowL = (lane & 15);
    const int aKbL  = (lane >> 4) * 16;
    const int bRowL = ((lane >> 4) << 3) + (lane & 7);
    const int bKbL  = ((lane >> 3) & 1) * 16;

    // Stage issue: 4 tiles of 128 rows x 32 bf16 (64B rows); 2 chunks/thread/tile
#define ISSUE_STAGE(kc, buf) do {                                              \
    uint32_t st = sb + (buf) * STAGE_BYTES;                                    \
    _Pragma("unroll")                                                          \
    for (int t = 0; t < 2; t++) {                                              \
        int idx = tid + t * 256;                                               \
        int row = idx >> 2, seg = idx & 3;                                     \
        int sw = SWZ64(row * 64 + seg * 16);                                   \
        size_t ga = (size_t)(blockRow + row) * FD + (kc) * 32 + seg * 8;       \
        size_t gb = (size_t)(blockCol + row) * FD + (kc) * 32 + seg * 8;       \
        cpasync16(st + 0     + sw, g_Ahi + ga);                                \
        cpasync16(st + 8192  + sw, g_Alo + ga);                                \
        cpasync16(st + 16384 + sw, Wh + gb);                                   \
        cpasync16(st + 24576 + sw, Wl + gb);                                   \
    }                                                                          \
    CP_COMMIT(); } while (0)

    ISSUE_STAGE(0, 0);

    for (int kc = 0; kc < FD / 32; kc++) {
        const int buf = kc & 1;
        if (kc < FD / 32 - 1) {
            ISSUE_STAGE(kc + 1, buf ^ 1);
            asm volatile("cp.async.wait_group 1;");
        } else {
            asm volatile("cp.async.wait_group 0;");
        }
        __syncthreads();

        const uint32_t st = sb + buf * STAGE_BYTES;
#pragma unroll
        for (int s = 0; s < 2; s++) {
            uint32_t bh[8], bl[8];
#pragma unroll
            for (int p = 0; p < 2; p++) {
                int brow = warp_n + p * 16 + bRowL;
                int boff = SWZ64(brow * 64 + s * 32 + bKbL);
                ldmx4(st + 16384 + boff, &bh[p * 4]);
                ldmx4(st + 24576 + boff, &bl[p * 4]);
            }
#pragma unroll
            for (int mt = 0; mt < 4; mt++) {
                int arow = warp_m + mt * 16 + aRowL;
                int aoff = SWZ64(arow * 64 + s * 32 + aKbL);
                uint32_t ah[4], al[4];
                ldmx4(st + 0 + aoff, ah);
                ldmx4(st + 8192 + aoff, al);
#pragma unroll
                for (int nt = 0; nt < 4; nt++) {
                    mma_bf16(acc[mt][nt], ah, &bh[nt * 2]);
                    mma_bf16(acc[mt][nt], ah, &bl[nt * 2]);
                    mma_bf16(acc[mt][nt], al, &bh[nt * 2]);
                }
            }
        }
        __syncthreads();
    }
#undef ISSUE_STAGE

    // Epilogue: c0,c1 -> (m, n..n+1); c2,c3 -> (m+8, n..n+1)
    const int mBase = blockRow + warp_m + (lane >> 2);
    const int nBase = blockCol + warp_n + (lane & 3) * 2;
#pragma unroll
    for (int mt = 0; mt < 4; mt++) {
        int m0 = mBase + mt * 16;
#pragma unroll
        for (int nt = 0; nt < 4; nt++) {
            int n = nBase + nt * 8;
            if (m0 < NN)
                *(float2*)(g_bufA + (size_t)m0 * FD + n) =
                    make_float2(acc[mt][nt][0], acc[mt][nt][1]);
            if (m0 + 8 < NN)
                *(float2*)(g_bufA + (size_t)(m0 + 8) * FD + n) =
                    make_float2(acc[mt][nt][2], acc[mt][nt][3]);
        }
    }
}

// ----------------------------------------------------------------------------
// Aggregation: acc = sum norm*g_bufA[src] + dinv^2*g_bufA[node] + bias, ReLU.
// SPLIT=true: write bf16 hi/lo into g_Ahi/g_Alo (feeds next GEMM directly).
// SPLIT=false: write fp32 into g_bufB (feeds the head).
// ----------------------------------------------------------------------------
template <bool SPLIT>
__global__ __launch_bounds__(128)
void agg_kernel(const float* __restrict__ bias) {
    const float* h = (const float*)g_bufA;
    int node = blockIdx.x;
    int t = threadIdx.x;
    __shared__ int   s_src[128];
    __shared__ float s_w[128];

    float dd = g_dinv[node];
    float4 acc;
    {
        float4 v = *(const float4*)(h + (size_t)node * FD + t * 4);
        float w = dd * dd;
        acc = make_float4(v.x * w, v.y * w, v.z * w, v.w * w);
    }

    int beg = g_row_start[node];
    int end = g_row_start[node + 1];
    for (int c = beg; c < end; c += 128) {
        int n = min(end - c, 128);
        if (t < n) {
            int s = g_csr_src[c + t];
            s_src[t] = s;
            s_w[t] = g_dinv[s] * dd;
        }
        __syncthreads();
        int e = 0;
        for (; e + 1 < n; e += 2) {
            int s0 = s_src[e],     s1 = s_src[e + 1];
            float w0 = s_w[e],     w1 = s_w[e + 1];
            float4 v0 = *(const float4*)(h + (size_t)s0 * FD + t * 4);
            float4 v1 = *(const float4*)(h + (size_t)s1 * FD + t * 4);
            acc.x += w0 * v0.x + w1 * v1.x;
            acc.y += w0 * v0.y + w1 * v1.y;
            acc.z += w0 * v0.z + w1 * v1.z;
            acc.w += w0 * v0.w + w1 * v1.w;
        }
        if (e < n) {
            int s0 = s_src[e];
            float w0 = s_w[e];
            float4 v0 = *(const float4*)(h + (size_t)s0 * FD + t * 4);
            acc.x += w0 * v0.x; acc.y += w0 * v0.y;
            acc.z += w0 * v0.z; acc.w += w0 * v0.w;
        }
        __syncthreads();
    }

    float4 b = *(const float4*)(bias + t * 4);
    acc.x = fmaxf(acc.x + b.x, 0.f);
    acc.y = fmaxf(acc.y + b.y, 0.f);
    acc.z = fmaxf(acc.z + b.z, 0.f);
    acc.w = fmaxf(acc.w + b.w, 0.f);

    size_t o = (size_t)node * FD + t * 4;
    if (SPLIT) {
        uint2 hi, lo;
        split4(acc, hi, lo);
        *(uint2*)(g_Ahi + o) = hi;
        *(uint2*)(g_Alo + o) = lo;
    } else {
        *(float4*)(g_bufB + o) = acc;
    }
}

// ----------------------------------------------------------------------------
// Final linear: out[N x 16] = g_bufB @ Wl + bl
// ----------------------------------------------------------------------------
__global__ __launch_bounds__(256)
void linear16_kernel(const float* __restrict__ W, const float* __restrict__ b,
                     float* __restrict__ out) {
    const float* h = (const float*)g_bufB;
    __shared__ float sW[FD * OUTD];
    int t = threadIdx.x;
    for (int i = t; i < FD * OUTD; i += 256) sW[i] = W[i];
    __syncthreads();

    int r = t >> 4;
    int c = t & 15;
    int row = blockIdx.x * 16 + r;
    if (row >= NN) return;

    const float4* hp = (const float4*)(h + (size_t)row * FD);
    float acc = 0.f;
#pragma unroll 4
    for (int k = 0; k < FD / 4; k++) {
        float4 v = hp[k];
        acc += v.x * sW[(4 * k + 0) * OUTD + c];
        acc += v.y * sW[(4 * k + 1) * OUTD + c];
        acc += v.z * sW[(4 * k + 2) * OUTD + c];
        acc += v.w * sW[(4 * k + 3) * OUTD + c];
    }
    out[(size_t)row * OUTD + c] = acc + b[c];
}

// ----------------------------------------------------------------------------
// Launch
// ----------------------------------------------------------------------------
extern "C" void kernel_launch(void* const* d_in, const int* in_sizes, int n_in,
                              void* d_out, int out_size) {
    const float* x  = (const float*)d_in[0];
    const int*   ei = (const int*)d_in[1];
    const float* W1 = (const float*)d_in[2];
    const float* b1 = (const float*)d_in[3];
    const float* W2 = (const float*)d_in[4];
    const float* b2 = (const float*)d_in[5];
    const float* Wl = (const float*)d_in[6];
    const float* bl = (const float*)d_in[7];
    float* out = (float*)d_out;

    cudaFuncSetAttribute(gemm_mma_kernel<0>,
                         cudaFuncAttributeMaxDynamicSharedMemorySize, GEMM_SMEM);
    cudaFuncSetAttribute(gemm_mma_kernel<1>,
                         cudaFuncAttributeMaxDynamicSharedMemorySize, GEMM_SMEM);

    // Graph preprocessing (CSR by destination)
    zero_counts_kernel<<<(NN + 255) / 256, 256>>>();
    count_kernel<<<(NE + 255) / 256, 256>>>(ei);
    scan_kernel<<<1, 1024>>>();
    fill_kernel<<<(NE + 255) / 256, 256>>>(ei);

    // Weight + input conversions
    convw_kernel<<<(2 * FD * FD + 255) / 256, 256>>>(W1, W2);
    conva_kernel<<<(int)(((size_t)M_PAD * FD / 4 + 255) / 256), 256>>>(x);

    dim3 gemmGrid(FD / 128, M_PAD / 128);                 // (4, 79)

    // Layer 1: bufA = split(x) @ W1 ; Ahi/Alo = split(relu(agg(bufA) + b1))
    gemm_mma_kernel<0><<<gemmGrid, 256, GEMM_SMEM>>>();
    agg_kernel<true><<<NN, 128>>>(b1);

    // Layer 2: bufA = split(h1) @ W2 ; bufB = relu(agg(bufA) + b2)
    gemm_mma_kernel<1><<<gemmGrid, 256, GEMM_SMEM>>>();
    agg_kernel<false><<<NN, 128>>>(b2);

    // Head
    linear16_kernel<<<(NN + 15) / 16, 256>>>(Wl, bl, out);
}

// round 9
// speedup vs baseline: 2.3725x; 1.0657x over previous
#include <cuda_runtime.h>
#include <cuda_bf16.h>
#include <cstdint>

// Problem constants (fixed by the dataset)
#define NN 10000      // nodes
#define NE 160000     // directed edges
#define FD 512        // feature dim (IN == H == 512)
#define OUTD 16       // classes
#define M_PAD 10112   // 79 * 128 (padded M for GEMM tiles)

// ----------------------------------------------------------------------------
// Scratch: __device__ globals (no runtime allocation allowed).
// ----------------------------------------------------------------------------
__device__ int   g_deg[NN];
__device__ int   g_cursor[NN];
__device__ float g_dinv[NN];
__device__ int   g_row_start[NN + 1];
__device__ int   g_csr_src[NE];
__device__ __align__(16) float g_bufA[(size_t)NN * FD];   // GEMM out (fp32)
__device__ __align__(16) float g_bufB[(size_t)NN * FD];   // agg2 out (fp32)
__device__ __align__(16) __nv_bfloat16 g_Ahi[(size_t)M_PAD * FD];
__device__ __align__(16) __nv_bfloat16 g_Alo[(size_t)M_PAD * FD];
__device__ __align__(16) __nv_bfloat16 g_Whi[2][FD * FD]; // transposed [N][K]
__device__ __align__(16) __nv_bfloat16 g_Wlo[2][FD * FD]; // transposed [N][K]

// SW64 swizzle on byte offsets (64B rows): XOR bits[5:4] with bits[8:7]
#define SWZ64(o) ((o) ^ (((o) >> 3) & 0x30))

__device__ __forceinline__ uint32_t smem_u32(const void* p) {
    uint32_t a;
    asm("{ .reg .u64 t; cvta.to.shared.u64 t, %1; cvt.u32.u64 %0, t; }"
        : "=r"(a) : "l"(p));
    return a;
}
__device__ __forceinline__ void ldmx4(uint32_t addr, uint32_t* r) {
    asm volatile("ldmatrix.sync.aligned.m8n8.x4.shared.b16 {%0,%1,%2,%3}, [%4];"
                 : "=r"(r[0]), "=r"(r[1]), "=r"(r[2]), "=r"(r[3]) : "r"(addr));
}
__device__ __forceinline__ void mma_bf16(float* c, const uint32_t* a,
                                         const uint32_t* b) {
    asm volatile(
        "mma.sync.aligned.m16n8k16.row.col.f32.bf16.bf16.f32 "
        "{%0,%1,%2,%3},{%4,%5,%6,%7},{%8,%9},{%0,%1,%2,%3};"
        : "+f"(c[0]), "+f"(c[1]), "+f"(c[2]), "+f"(c[3])
        : "r"(a[0]), "r"(a[1]), "r"(a[2]), "r"(a[3]), "r"(b[0]), "r"(b[1]));
}
__device__ __forceinline__ void cpasync16(uint32_t s, const void* g) {
    asm volatile("cp.async.cg.shared.global [%0], [%1], 16;" :: "r"(s), "l"(g));
}
#define CP_COMMIT() asm volatile("cp.async.commit_group;")

// Per-block edge_index dtype detection: if buffer is int64, odd words of the
// first 32 elements are high words of values < 2^31 -> all zero.
__device__ __forceinline__ int detect_i64(const int* __restrict__ ei32) {
    int o = 0;
#pragma unroll
    for (int j = 0; j < 32; j++) o |= ei32[2 * j + 1];
    return (o == 0) ? 1 : 0;
}

// ----------------------------------------------------------------------------
// Graph preprocessing
// ----------------------------------------------------------------------------
__global__ void zero_counts_kernel() {
    int i = blockIdx.x * blockDim.x + threadIdx.x;
    if (i < NN) { g_deg[i] = 0; g_cursor[i] = 0; }
}

__global__ void count_kernel(const int* __restrict__ ei32) {
    __shared__ int s_i64;
    if (threadIdx.x == 0) s_i64 = detect_i64(ei32);
    __syncthreads();
    int i = blockIdx.x * blockDim.x + threadIdx.x;
    if (i < NE) {
        int dst = s_i64 ? ei32[2 * (NE + i)] : ei32[NE + i];
        atomicAdd(&g_deg[dst], 1);
    }
}

// Single-block exclusive scan of g_deg -> g_row_start.
__global__ void scan_kernel() {
    __shared__ int sums[1024];
    const int CH = (NN + 1023) / 1024;   // 10
    int t = threadIdx.x;
    int start = t * CH;
    int vals[CH];
    int local = 0;
#pragma unroll
    for (int i = 0; i < CH; i++) {
        int idx = start + i;
        int v = (idx < NN) ? g_deg[idx] : 0;
        vals[i] = v;
        local += v;
    }
    sums[t] = local;
    __syncthreads();
    for (int off = 1; off < 1024; off <<= 1) {
        int v = sums[t];
        int add = (t >= off) ? sums[t - off] : 0;
        __syncthreads();
        sums[t] = v + add;
        __syncthreads();
    }
    int prefix = (t == 0) ? 0 : sums[t - 1];
#pragma unroll
    for (int i = 0; i < CH; i++) {
        int idx = start + i;
        if (idx < NN) { g_row_start[idx] = prefix; prefix += vals[i]; }
    }
    if (t == 1023) g_row_start[NN] = prefix;
}

// CSR fill + grid-wide dinv.
__global__ void fill_kernel(const int* __restrict__ ei32) {
    __shared__ int s_i64;
    if (threadIdx.x == 0) s_i64 = detect_i64(ei32);
    __syncthreads();
    int i = blockIdx.x * blockDim.x + threadIdx.x;
    if (i < NE) {
        int src, dst;
        if (s_i64) { src = ei32[2 * i]; dst = ei32[2 * (NE + i)]; }
        else       { src = ei32[i];     dst = ei32[NE + i]; }
        int pos = atomicAdd(&g_cursor[dst], 1);
        g_csr_src[g_row_start[dst] + pos] = src;
    }
    for (int n = i; n < NN; n += gridDim.x * blockDim.x)
        g_dinv[n] = rsqrtf((float)g_deg[n] + 1.0f);
}

// ----------------------------------------------------------------------------
// fp32 -> bf16 hi/lo split conversions (merged: A split + both W transposes)
// ----------------------------------------------------------------------------
__device__ __forceinline__ uint32_t pk2(__nv_bfloat16 a, __nv_bfloat16 b) {
    __nv_bfloat162 t(a, b);
    return *reinterpret_cast<uint32_t*>(&t);
}
__device__ __forceinline__ void split4(float4 v, uint2& hi, uint2& lo) {
    __nv_bfloat16 h0 = __float2bfloat16(v.x), h1 = __float2bfloat16(v.y);
    __nv_bfloat16 h2 = __float2bfloat16(v.z), h3 = __float2bfloat16(v.w);
    __nv_bfloat16 l0 = __float2bfloat16(v.x - __bfloat162float(h0));
    __nv_bfloat16 l1 = __float2bfloat16(v.y - __bfloat162float(h1));
    __nv_bfloat16 l2 = __float2bfloat16(v.z - __bfloat162float(h2));
    __nv_bfloat16 l3 = __float2bfloat16(v.w - __bfloat162float(h3));
    hi = make_uint2(pk2(h0, h1), pk2(h2, h3));
    lo = make_uint2(pk2(l0, l1), pk2(l2, l3));
}

#define CONVA_ITEMS ((M_PAD * FD) / 4)       // vec4 items for A
#define CONVW_ITEMS (2 * FD * FD)            // scalar items for both W

__global__ __launch_bounds__(256)
void conv_kernel(const float* __restrict__ x, const float* __restrict__ W1,
                 const float* __restrict__ W2) {
    int idx = blockIdx.x * blockDim.x + threadIdx.x;
    if (idx < CONVA_ITEMS) {
        size_t i = (size_t)idx * 4;
        int row = (int)(i >> 9);
        float4 v = make_float4(0.f, 0.f, 0.f, 0.f);
        if (row < NN) v = *(const float4*)(x + i);
        uint2 hi, lo;
        split4(v, hi, lo);
        *(uint2*)(g_Ahi + i) = hi;
        *(uint2*)(g_Alo + i) = lo;
    } else {
        int j = idx - CONVA_ITEMS;
        if (j < CONVW_ITEMS) {
            int layer = j >> 18;                 // / (FD*FD)
            int r = j & (FD * FD - 1);           // output index n*512 + k
            int n = r >> 9, k = r & (FD - 1);
            const float* W = layer ? W2 : W1;
            float v = W[(size_t)k * FD + n];
            __nv_bfloat16 hi = __float2bfloat16(v);
            g_Whi[layer][r] = hi;
            g_Wlo[layer][r] = __float2bfloat16(v - __bfloat162float(hi));
        }
    }
}

// ----------------------------------------------------------------------------
// Split-precision bf16 GEMM via mma.sync, cp.async 2-stage pipeline (as R8):
//   g_bufA[M_PAD x 512] = Ahi@Whi^T + Ahi@Wlo^T + Alo@Whi^T   (fp32 accum)
// ----------------------------------------------------------------------------
#define STAGE_BYTES 32768
#define GEMM_SMEM   (2 * STAGE_BYTES)

template <int LAYER>
__global__ __launch_bounds__(256, 2)
void gemm_mma_kernel() {
    extern __shared__ __align__(1024) char smem[];
    const uint32_t sb = smem_u32(smem);

    const int tid = threadIdx.x;
    const int wid = tid >> 5;
    const int lane = tid & 31;
    const int warp_m = (wid & 1) * 64;
    const int warp_n = (wid >> 1) * 32;
    const int blockCol = blockIdx.x * 128;
    const int blockRow = blockIdx.y * 128;

    const __nv_bfloat16* Wh = g_Whi[LAYER];
    const __nv_bfloat16* Wl = g_Wlo[LAYER];

    float acc[4][4][4];
#pragma unroll
    for (int i = 0; i < 4; i++)
#pragma unroll
        for (int j = 0; j < 4; j++)
#pragma unroll
            for (int k = 0; k < 4; k++) acc[i][j][k] = 0.f;

    const int aRowL = (lane & 15);
    const int aKbL  = (lane >> 4) * 16;
    const int bRowL = ((lane >> 4) << 3) + (lane & 7);
    const int bKbL  = ((lane >> 3) & 1) * 16;

#define ISSUE_STAGE(kc, buf) do {                                              \
    uint32_t st = sb + (buf) * STAGE_BYTES;                                    \
    _Pragma("unroll")                                                          \
    for (int t = 0; t < 2; t++) {                                              \
        int idx = tid + t * 256;                                               \
        int row = idx >> 2, seg = idx & 3;                                     \
        int sw = SWZ64(row * 64 + seg * 16);                                   \
        size_t ga = (size_t)(blockRow + row) * FD + (kc) * 32 + seg * 8;       \
        size_t gb = (size_t)(blockCol + row) * FD + (kc) * 32 + seg * 8;       \
        cpasync16(st + 0     + sw, g_Ahi + ga);                                \
        cpasync16(st + 8192  + sw, g_Alo + ga);                                \
        cpasync16(st + 16384 + sw, Wh + gb);                                   \
        cpasync16(st + 24576 + sw, Wl + gb);                                   \
    }                                                                          \
    CP_COMMIT(); } while (0)

    ISSUE_STAGE(0, 0);

    for (int kc = 0; kc < FD / 32; kc++) {
        const int buf = kc & 1;
        if (kc < FD / 32 - 1) {
            ISSUE_STAGE(kc + 1, buf ^ 1);
            asm volatile("cp.async.wait_group 1;");
        } else {
            asm volatile("cp.async.wait_group 0;");
        }
        __syncthreads();

        const uint32_t st = sb + buf * STAGE_BYTES;
#pragma unroll
        for (int s = 0; s < 2; s++) {
            uint32_t bh[8], bl[8];
#pragma unroll
            for (int p = 0; p < 2; p++) {
                int brow = warp_n + p * 16 + bRowL;
                int boff = SWZ64(brow * 64 + s * 32 + bKbL);
                ldmx4(st + 16384 + boff, &bh[p * 4]);
                ldmx4(st + 24576 + boff, &bl[p * 4]);
            }
#pragma unroll
            for (int mt = 0; mt < 4; mt++) {
                int arow = warp_m + mt * 16 + aRowL;
                int aoff = SWZ64(arow * 64 + s * 32 + aKbL);
                uint32_t ah[4], al[4];
                ldmx4(st + 0 + aoff, ah);
                ldmx4(st + 8192 + aoff, al);
#pragma unroll
                for (int nt = 0; nt < 4; nt++) {
                    mma_bf16(acc[mt][nt], ah, &bh[nt * 2]);
                    mma_bf16(acc[mt][nt], ah, &bl[nt * 2]);
                    mma_bf16(acc[mt][nt], al, &bh[nt * 2]);
                }
            }
        }
        __syncthreads();
    }
#undef ISSUE_STAGE

    const int mBase = blockRow + warp_m + (lane >> 2);
    const int nBase = blockCol + warp_n + (lane & 3) * 2;
#pragma unroll
    for (int mt = 0; mt < 4; mt++) {
        int m0 = mBase + mt * 16;
#pragma unroll
        for (int nt = 0; nt < 4; nt++) {
            int n = nBase + nt * 8;
            if (m0 < NN)
                *(float2*)(g_bufA + (size_t)m0 * FD + n) =
                    make_float2(acc[mt][nt][0], acc[mt][nt][1]);
            if (m0 + 8 < NN)
                *(float2*)(g_bufA + (size_t)(m0 + 8) * FD + n) =
                    make_float2(acc[mt][nt][2], acc[mt][nt][3]);
        }
    }
}

// ----------------------------------------------------------------------------
// Aggregation: acc = sum norm*g_bufA[src] + dinv^2*g_bufA[node] + bias, ReLU.
// Unroll x4 for MLP; __ldcg (L2-only) on gathered rows (no L1 reuse).
// SPLIT=true: write bf16 hi/lo into g_Ahi/g_Alo. SPLIT=false: fp32 g_bufB.
// ----------------------------------------------------------------------------
template <bool SPLIT>
__global__ __launch_bounds__(128)
void agg_kernel(const float* __restrict__ bias) {
    const float* h = (const float*)g_bufA;
    int node = blockIdx.x;
    int t = threadIdx.x;
    __shared__ int   s_src[128];
    __shared__ float s_w[128];

    float dd = g_dinv[node];
    float4 acc;
    {
        float4 v = __ldcg((const float4*)(h + (size_t)node * FD) + t);
        float w = dd * dd;
        acc = make_float4(v.x * w, v.y * w, v.z * w, v.w * w);
    }

    int beg = g_row_start[node];
    int end = g_row_start[node + 1];
    for (int c = beg; c < end; c += 128) {
        int n = min(end - c, 128);
        if (t < n) {
            int s = g_csr_src[c + t];
            s_src[t] = s;
            s_w[t] = g_dinv[s] * dd;
        }
        __syncthreads();
        int e = 0;
        for (; e + 3 < n; e += 4) {
            int s0 = s_src[e],     s1 = s_src[e + 1];
            int s2 = s_src[e + 2], s3 = s_src[e + 3];
            float w0 = s_w[e],     w1 = s_w[e + 1];
            float w2 = s_w[e + 2], w3 = s_w[e + 3];
            float4 v0 = __ldcg((const float4*)(h + (size_t)s0 * FD) + t);
            float4 v1 = __ldcg((const float4*)(h + (size_t)s1 * FD) + t);
            float4 v2 = __ldcg((const float4*)(h + (size_t)s2 * FD) + t);
            float4 v3 = __ldcg((const float4*)(h + (size_t)s3 * FD) + t);
            acc.x += w0 * v0.x + w1 * v1.x + w2 * v2.x + w3 * v3.x;
            acc.y += w0 * v0.y + w1 * v1.y + w2 * v2.y + w3 * v3.y;
            acc.z += w0 * v0.z + w1 * v1.z + w2 * v2.z + w3 * v3.z;
            acc.w += w0 * v0.w + w1 * v1.w + w2 * v2.w + w3 * v3.w;
        }
        for (; e < n; e++) {
            int s0 = s_src[e];
            float w0 = s_w[e];
            float4 v0 = __ldcg((const float4*)(h + (size_t)s0 * FD) + t);
            acc.x += w0 * v0.x; acc.y += w0 * v0.y;
            acc.z += w0 * v0.z; acc.w += w0 * v0.w;
        }
        __syncthreads();
    }

    float4 b = *(const float4*)(bias + t * 4);
    acc.x = fmaxf(acc.x + b.x, 0.f);
    acc.y = fmaxf(acc.y + b.y, 0.f);
    acc.z = fmaxf(acc.z + b.z, 0.f);
    acc.w = fmaxf(acc.w + b.w, 0.f);

    size_t o = (size_t)node * FD + t * 4;
    if (SPLIT) {
        uint2 hi, lo;
        split4(acc, hi, lo);
        *(uint2*)(g_Ahi + o) = hi;
        *(uint2*)(g_Alo + o) = lo;
    } else {
        *(float4*)(g_bufB + o) = acc;
    }
}

// ----------------------------------------------------------------------------
// Final linear: out[N x 16] = g_bufB @ Wl + bl
// ----------------------------------------------------------------------------
__global__ __launch_bounds__(256)
void linear16_kernel(const float* __restrict__ W, const float* __restrict__ b,
                     float* __restrict__ out) {
    const float* h = (const float*)g_bufB;
    __shared__ float sW[FD * OUTD];
    int t = threadIdx.x;
    for (int i = t; i < FD * OUTD; i += 256) sW[i] = W[i];
    __syncthreads();

    int r = t >> 4;
    int c = t & 15;
    int row = blockIdx.x * 16 + r;
    if (row >= NN) return;

    const float4* hp = (const float4*)(h + (size_t)row * FD);
    float acc = 0.f;
#pragma unroll 4
    for (int k = 0; k < FD / 4; k++) {
        float4 v = hp[k];
        acc += v.x * sW[(4 * k + 0) * OUTD + c];
        acc += v.y * sW[(4 * k + 1) * OUTD + c];
        acc += v.z * sW[(4 * k + 2) * OUTD + c];
        acc += v.w * sW[(4 * k + 3) * OUTD + c];
    }
    out[(size_t)row * OUTD + c] = acc + b[c];
}

// ----------------------------------------------------------------------------
// Side stream + events for fork/join overlap (created once at static init,
// before the harness's memory checkpoints; no device memory involved).
// ----------------------------------------------------------------------------
namespace {
struct Aux {
    cudaStream_t s2 = nullptr;
    cudaEvent_t  eFork = nullptr, eJoin = nullptr;
    bool ok = false;
    Aux() {
        if (cudaStreamCreateWithFlags(&s2, cudaStreamNonBlocking) != cudaSuccess)
            return;
        if (cudaEventCreateWithFlags(&eFork, cudaEventDisableTiming) != cudaSuccess)
            return;
        if (cudaEventCreateWithFlags(&eJoin, cudaEventDisableTiming) != cudaSuccess)
            return;
        ok = true;
    }
};
Aux g_aux;
}

// ----------------------------------------------------------------------------
// Launch
// ----------------------------------------------------------------------------
extern "C" void kernel_launch(void* const* d_in, const int* in_sizes, int n_in,
                              void* d_out, int out_size) {
    const float* x  = (const float*)d_in[0];
    const int*   ei = (const int*)d_in[1];
    const float* W1 = (const float*)d_in[2];
    const float* b1 = (const float*)d_in[3];
    const float* W2 = (const float*)d_in[4];
    const float* b2 = (const float*)d_in[5];
    const float* Wl = (const float*)d_in[6];
    const float* bl = (const float*)d_in[7];
    float* out = (float*)d_out;

    cudaFuncSetAttribute(gemm_mma_kernel<0>,
                         cudaFuncAttributeMaxDynamicSharedMemorySize, GEMM_SMEM);
    cudaFuncSetAttribute(gemm_mma_kernel<1>,
                         cudaFuncAttributeMaxDynamicSharedMemorySize, GEMM_SMEM);

    dim3 gemmGrid(FD / 128, M_PAD / 128);                 // (4, 79)
    int convBlocks = (CONVA_ITEMS + CONVW_ITEMS + 255) / 256;

    if (g_aux.ok) {
        // Fork: CSR preprocessing on side stream, conversions + GEMM-0 on main.
        cudaEventRecord(g_aux.eFork, 0);
        cudaStreamWaitEvent(g_aux.s2, g_aux.eFork, 0);
        zero_counts_kernel<<<(NN + 255) / 256, 256, 0, g_aux.s2>>>();
        count_kernel<<<(NE + 255) / 256, 256, 0, g_aux.s2>>>(ei);
        scan_kernel<<<1, 1024, 0, g_aux.s2>>>();
        fill_kernel<<<(NE + 255) / 256, 256, 0, g_aux.s2>>>(ei);
        cudaEventRecord(g_aux.eJoin, g_aux.s2);

        conv_kernel<<<convBlocks, 256>>>(x, W1, W2);
        gemm_mma_kernel<0><<<gemmGrid, 256, GEMM_SMEM>>>();

        cudaStreamWaitEvent(0, g_aux.eJoin, 0);           // join before agg
    } else {
        // Serial fallback
        zero_counts_kernel<<<(NN + 255) / 256, 256>>>();
        count_kernel<<<(NE + 255) / 256, 256>>>(ei);
        scan_kernel<<<1, 1024>>>();
        fill_kernel<<<(NE + 255) / 256, 256>>>(ei);
        conv_kernel<<<convBlocks, 256>>>(x, W1, W2);
        gemm_mma_kernel<0><<<gemmGrid, 256, GEMM_SMEM>>>();
    }

    // Layer 1 aggregation -> bf16 split input of layer 2
    agg_kernel<true><<<NN, 128>>>(b1);

    // Layer 2
    gemm_mma_kernel<1><<<gemmGrid, 256, GEMM_SMEM>>>();
    agg_kernel<false><<<NN, 128>>>(b2);

    // Head
    linear16_kernel<<<(NN + 15) / 16, 256>>>(Wl, bl, out);
}

// round 11
// speedup vs baseline: 2.5058x; 1.0562x over previous
#include <cuda_runtime.h>
#include <cuda_bf16.h>
#include <cstdint>

// Problem constants (fixed by the dataset)
#define NN 10000      // nodes
#define NE 160000     // directed edges
#define FD 512        // feature dim (IN == H == 512)
#define OUTD 16       // classes
#define BM 144        // GEMM M tile (9 x 16)
#define MTILES 71     // ceil(10000 / 144)
#define M_PAD (BM * MTILES)   // 10224

// ----------------------------------------------------------------------------
// Scratch: __device__ globals (no runtime allocation allowed).
// ----------------------------------------------------------------------------
__device__ int   g_deg[NN];
__device__ int   g_cursor[NN];
__device__ float g_dinv[NN];
__device__ int   g_row_start[NN + 1];
__device__ int   g_csr_src[NE];
__device__ __align__(16) float g_bufA[(size_t)NN * FD];   // GEMM out (fp32)
__device__ __align__(16) float g_bufB[(size_t)NN * FD];   // agg2 out (fp32)
__device__ __align__(16) __nv_bfloat16 g_Ahi[(size_t)M_PAD * FD];
__device__ __align__(16) __nv_bfloat16 g_Alo[(size_t)M_PAD * FD];
__device__ __align__(16) __nv_bfloat16 g_Whi[2][FD * FD]; // transposed [N][K]
__device__ __align__(16) __nv_bfloat16 g_Wlo[2][FD * FD]; // transposed [N][K]

// SW64 swizzle on byte offsets (64B rows): XOR bits[5:4] with bits[8:7]
#define SWZ64(o) ((o) ^ (((o) >> 3) & 0x30))

__device__ __forceinline__ uint32_t smem_u32(const void* p) {
    uint32_t a;
    asm("{ .reg .u64 t; cvta.to.shared.u64 t, %1; cvt.u32.u64 %0, t; }"
        : "=r"(a) : "l"(p));
    return a;
}
__device__ __forceinline__ void ldmx4(uint32_t addr, uint32_t* r) {
    asm volatile("ldmatrix.sync.aligned.m8n8.x4.shared.b16 {%0,%1,%2,%3}, [%4];"
                 : "=r"(r[0]), "=r"(r[1]), "=r"(r[2]), "=r"(r[3]) : "r"(addr));
}
__device__ __forceinline__ void mma_bf16(float* c, const uint32_t* a,
                                         const uint32_t* b) {
    asm volatile(
        "mma.sync.aligned.m16n8k16.row.col.f32.bf16.bf16.f32 "
        "{%0,%1,%2,%3},{%4,%5,%6,%7},{%8,%9},{%0,%1,%2,%3};"
        : "+f"(c[0]), "+f"(c[1]), "+f"(c[2]), "+f"(c[3])
        : "r"(a[0]), "r"(a[1]), "r"(a[2]), "r"(a[3]), "r"(b[0]), "r"(b[1]));
}
__device__ __forceinline__ void cpasync16(uint32_t s, const void* g) {
    asm volatile("cp.async.cg.shared.global [%0], [%1], 16;" :: "r"(s), "l"(g));
}
#define CP_COMMIT() asm volatile("cp.async.commit_group;")

// Per-block edge_index dtype detection: if buffer is int64, odd words of the
// first 32 elements are high words of values < 2^31 -> all zero.
__device__ __forceinline__ int detect_i64(const int* __restrict__ ei32) {
    int o = 0;
#pragma unroll
    for (int j = 0; j < 32; j++) o |= ei32[2 * j + 1];
    return (o == 0) ? 1 : 0;
}

// ----------------------------------------------------------------------------
// Graph preprocessing
// ----------------------------------------------------------------------------
__global__ void zero_counts_kernel() {
    int i = blockIdx.x * blockDim.x + threadIdx.x;
    if (i < NN) { g_deg[i] = 0; g_cursor[i] = 0; }
}

__global__ void count_kernel(const int* __restrict__ ei32) {
    __shared__ int s_i64;
    if (threadIdx.x == 0) s_i64 = detect_i64(ei32);
    __syncthreads();
    int i = blockIdx.x * blockDim.x + threadIdx.x;
    if (i < NE) {
        int dst = s_i64 ? ei32[2 * (NE + i)] : ei32[NE + i];
        atomicAdd(&g_deg[dst], 1);
    }
}

// Single-block exclusive scan of g_deg -> g_row_start.
__global__ void scan_kernel() {
    __shared__ int sums[1024];
    const int CH = (NN + 1023) / 1024;   // 10
    int t = threadIdx.x;
    int start = t * CH;
    int vals[CH];
    int local = 0;
#pragma unroll
    for (int i = 0; i < CH; i++) {
        int idx = start + i;
        int v = (idx < NN) ? g_deg[idx] : 0;
        vals[i] = v;
        local += v;
    }
    sums[t] = local;
    __syncthreads();
    for (int off = 1; off < 1024; off <<= 1) {
        int v = sums[t];
        int add = (t >= off) ? sums[t - off] : 0;
        __syncthreads();
        sums[t] = v + add;
        __syncthreads();
    }
    int prefix = (t == 0) ? 0 : sums[t - 1];
#pragma unroll
    for (int i = 0; i < CH; i++) {
        int idx = start + i;
        if (idx < NN) { g_row_start[idx] = prefix; prefix += vals[i]; }
    }
    if (t == 1023) g_row_start[NN] = prefix;
}

// CSR fill + grid-wide dinv.
__global__ void fill_kernel(const int* __restrict__ ei32) {
    __shared__ int s_i64;
    if (threadIdx.x == 0) s_i64 = detect_i64(ei32);
    __syncthreads();
    int i = blockIdx.x * blockDim.x + threadIdx.x;
    if (i < NE) {
        int src, dst;
        if (s_i64) { src = ei32[2 * i]; dst = ei32[2 * (NE + i)]; }
        else       { src = ei32[i];     dst = ei32[NE + i]; }
        int pos = atomicAdd(&g_cursor[dst], 1);
        g_csr_src[g_row_start[dst] + pos] = src;
    }
    for (int n = i; n < NN; n += gridDim.x * blockDim.x)
        g_dinv[n] = rsqrtf((float)g_deg[n] + 1.0f);
}

// ----------------------------------------------------------------------------
// fp32 -> bf16 hi/lo split conversions (merged: A split + both W transposes)
// ----------------------------------------------------------------------------
__device__ __forceinline__ uint32_t pk2(__nv_bfloat16 a, __nv_bfloat16 b) {
    __nv_bfloat162 t(a, b);
    return *reinterpret_cast<uint32_t*>(&t);
}
__device__ __forceinline__ void split4(float4 v, uint2& hi, uint2& lo) {
    __nv_bfloat16 h0 = __float2bfloat16(v.x), h1 = __float2bfloat16(v.y);
    __nv_bfloat16 h2 = __float2bfloat16(v.z), h3 = __float2bfloat16(v.w);
    __nv_bfloat16 l0 = __float2bfloat16(v.x - __bfloat162float(h0));
    __nv_bfloat16 l1 = __float2bfloat16(v.y - __bfloat162float(h1));
    __nv_bfloat16 l2 = __float2bfloat16(v.z - __bfloat162float(h2));
    __nv_bfloat16 l3 = __float2bfloat16(v.w - __bfloat162float(h3));
    hi = make_uint2(pk2(h0, h1), pk2(h2, h3));
    lo = make_uint2(pk2(l0, l1), pk2(l2, l3));
}

#define CONVA_ITEMS ((M_PAD * FD) / 4)       // vec4 items for A
#define CONVW_ITEMS (2 * FD * FD)            // scalar items for both W

__global__ __launch_bounds__(256)
void conv_kernel(const float* __restrict__ x, const float* __restrict__ W1,
                 const float* __restrict__ W2) {
    int idx = blockIdx.x * blockDim.x + threadIdx.x;
    if (idx < CONVA_ITEMS) {
        size_t i = (size_t)idx * 4;
        int row = (int)(i >> 9);
        float4 v = make_float4(0.f, 0.f, 0.f, 0.f);
        if (row < NN) v = *(const float4*)(x + i);
        uint2 hi, lo;
        split4(v, hi, lo);
        *(uint2*)(g_Ahi + i) = hi;
        *(uint2*)(g_Alo + i) = lo;
    } else {
        int j = idx - CONVA_ITEMS;
        if (j < CONVW_ITEMS) {
            int layer = j >> 18;                 // / (FD*FD)
            int r = j & (FD * FD - 1);           // output index n*512 + k
            int n = r >> 9, k = r & (FD - 1);
            const float* W = layer ? W2 : W1;
            float v = W[(size_t)k * FD + n];
            __nv_bfloat16 hi = __float2bfloat16(v);
            g_Whi[layer][r] = hi;
            g_Wlo[layer][r] = __float2bfloat16(v - __bfloat162float(hi));
        }
    }
}

// ----------------------------------------------------------------------------
// Split-precision bf16 GEMM via mma.sync, cp.async 2-stage pipeline:
//   g_bufA[M_PAD x 512] = Ahi@Whi^T + Ahi@Wlo^T + Alo@Whi^T   (fp32 accum)
// CTA tile 144x128 (BM=144 -> grid 4x71 = 284 CTAs = one resident wave at
// 2 CTAs/SM; per-SM max 2 tiles vs 2.05 avg). 384 threads = 12 warps
// (3 M-warps x 4 N-warps, warp tile 48x32). BK=32, SW64 64B rows.
// Stage = Ahi 9216 + Alo 9216 + Bhi 8192 + Blo 8192 = 34816 B; 2 stages.
// ----------------------------------------------------------------------------
#define OFF_ALO 9216
#define OFF_BHI 18432
#define OFF_BLO 26624
#define STAGE_BYTES 34816
#define GEMM_SMEM   (2 * STAGE_BYTES)

template <int LAYER>
__global__ __launch_bounds__(384, 2)
void gemm_mma_kernel() {
    extern __shared__ __align__(1024) char smem[];
    const uint32_t sb = smem_u32(smem);

    const int tid = threadIdx.x;
    const int wid = tid >> 5;
    const int lane = tid & 31;
    const int warp_m = (wid >> 2) * 48;      // 0, 48, 96
    const int warp_n = (wid & 3) * 32;       // 0, 32, 64, 96
    const int blockCol = blockIdx.x * 128;
    const int blockRow = blockIdx.y * BM;

    const __nv_bfloat16* Wh = g_Whi[LAYER];
    const __nv_bfloat16* Wl = g_Wlo[LAYER];

    float acc[3][4][4];
#pragma unroll
    for (int i = 0; i < 3; i++)
#pragma unroll
        for (int j = 0; j < 4; j++)
#pragma unroll
            for (int k = 0; k < 4; k++) acc[i][j][k] = 0.f;

    const int aRowL = (lane & 15);
    const int aKbL  = (lane >> 4) * 16;
    const int bRowL = ((lane >> 4) << 3) + (lane & 7);
    const int bKbL  = ((lane >> 3) & 1) * 16;

    // A: 1152 16B-chunks (Ahi 576 + Alo 576); B: 1024 (Bhi 512 + Blo 512)
#define ISSUE_STAGE(kc, buf) do {                                              \
    uint32_t st = sb + (buf) * STAGE_BYTES;                                    \
    _Pragma("unroll")                                                          \
    for (int t = 0; t < 3; t++) {                                              \
        int idx = tid + t * 384;             /* 0..1151 */                     \
        int mat = (idx >= 576);                                                \
        int r = idx - (mat ? 576 : 0);                                         \
        int row = r >> 2, seg = r & 3;                                         \
        int sw = SWZ64(row * 64 + seg * 16);                                   \
        size_t ga = (size_t)(blockRow + row) * FD + (kc) * 32 + seg * 8;       \
        cpasync16(st + (mat ? OFF_ALO : 0) + sw,                               \
                  (mat ? g_Alo : g_Ahi) + ga);                                 \
    }                                                                          \
    _Pragma("unroll")                                                          \
    for (int t = 0; t < 3; t++) {                                              \
        int idx = tid + t * 384;                                               \
        if (idx < 1024) {                                                      \
            int mat = (idx >= 512);                                            \
            int r = idx - (mat ? 512 : 0);                                     \
            int row = r >> 2, seg = r & 3;                                     \
            int sw = SWZ64(row * 64 + seg * 16);                               \
            size_t gb = (size_t)(blockCol + row) * FD + (kc) * 32 + seg * 8;   \
            cpasync16(st + (mat ? OFF_BLO : OFF_BHI) + sw,                     \
                      (mat ? Wl : Wh) + gb);                                   \
        }                                                                      \
    }                                                                          \
    CP_COMMIT(); } while (0)

    ISSUE_STAGE(0, 0);

    for (int kc = 0; kc < FD / 32; kc++) {
        const int buf = kc & 1;
        if (kc < FD / 32 - 1) {
            ISSUE_STAGE(kc + 1, buf ^ 1);
            asm volatile("cp.async.wait_group 1;");
        } else {
            asm volatile("cp.async.wait_group 0;");
        }
        __syncthreads();

        const uint32_t st = sb + buf * STAGE_BYTES;
#pragma unroll
        for (int s = 0; s < 2; s++) {
            uint32_t bh[8], bl[8];
#pragma unroll
            for (int p = 0; p < 2; p++) {
                int brow = warp_n + p * 16 + bRowL;
                int boff = SWZ64(brow * 64 + s * 32 + bKbL);
                ldmx4(st + OFF_BHI + boff, &bh[p * 4]);
                ldmx4(st + OFF_BLO + boff, &bl[p * 4]);
            }
#pragma unroll
            for (int mt = 0; mt < 3; mt++) {
                int arow = warp_m + mt * 16 + aRowL;
                int aoff = SWZ64(arow * 64 + s * 32 + aKbL);
                uint32_t ah[4], al[4];
                ldmx4(st + 0 + aoff, ah);
                ldmx4(st + OFF_ALO + aoff, al);
#pragma unroll
                for (int nt = 0; nt < 4; nt++) {
                    mma_bf16(acc[mt][nt], ah, &bh[nt * 2]);
                    mma_bf16(acc[mt][nt], ah, &bl[nt * 2]);
                    mma_bf16(acc[mt][nt], al, &bh[nt * 2]);
                }
            }
        }
        __syncthreads();
    }
#undef ISSUE_STAGE

    const int mBase = blockRow + warp_m + (lane >> 2);
    const int nBase = blockCol + warp_n + (lane & 3) * 2;
#pragma unroll
    for (int mt = 0; mt < 3; mt++) {
        int m0 = mBase + mt * 16;
#pragma unroll
        for (int nt = 0; nt < 4; nt++) {
            int n = nBase + nt * 8;
            if (m0 < NN)
                *(float2*)(g_bufA + (size_t)m0 * FD + n) =
                    make_float2(acc[mt][nt][0], acc[mt][nt][1]);
            if (m0 + 8 < NN)
                *(float2*)(g_bufA + (size_t)(m0 + 8) * FD + n) =
                    make_float2(acc[mt][nt][2], acc[mt][nt][3]);
        }
    }
}

// ----------------------------------------------------------------------------
// Aggregation: acc = sum norm*g_bufA[src] + dinv^2*g_bufA[node] + bias, ReLU.
// SPLIT=true: write bf16 hi/lo into g_Ahi/g_Alo. SPLIT=false: fp32 g_bufB.
// ----------------------------------------------------------------------------
template <bool SPLIT>
__global__ __launch_bounds__(128)
void agg_kernel(const float* __restrict__ bias) {
    const float* h = (const float*)g_bufA;
    int node = blockIdx.x;
    int t = threadIdx.x;
    __shared__ int   s_src[128];
    __shared__ float s_w[128];

    float dd = g_dinv[node];
    float4 acc;
    {
        float4 v = __ldcg((const float4*)(h + (size_t)node * FD) + t);
        float w = dd * dd;
        acc = make_float4(v.x * w, v.y * w, v.z * w, v.w * w);
    }

    int beg = g_row_start[node];
    int end = g_row_start[node + 1];
    for (int c = beg; c < end; c += 128) {
        int n = min(end - c, 128);
        if (t < n) {
            int s = g_csr_src[c + t];
            s_src[t] = s;
            s_w[t] = g_dinv[s] * dd;
        }
        __syncthreads();
        int e = 0;
        for (; e + 3 < n; e += 4) {
            int s0 = s_src[e],     s1 = s_src[e + 1];
            int s2 = s_src[e + 2], s3 = s_src[e + 3];
            float w0 = s_w[e],     w1 = s_w[e + 1];
            float w2 = s_w[e + 2], w3 = s_w[e + 3];
            float4 v0 = __ldcg((const float4*)(h + (size_t)s0 * FD) + t);
            float4 v1 = __ldcg((const float4*)(h + (size_t)s1 * FD) + t);
            float4 v2 = __ldcg((const float4*)(h + (size_t)s2 * FD) + t);
            float4 v3 = __ldcg((const float4*)(h + (size_t)s3 * FD) + t);
            acc.x += w0 * v0.x + w1 * v1.x + w2 * v2.x + w3 * v3.x;
            acc.y += w0 * v0.y + w1 * v1.y + w2 * v2.y + w3 * v3.y;
            acc.z += w0 * v0.z + w1 * v1.z + w2 * v2.z + w3 * v3.z;
            acc.w += w0 * v0.w + w1 * v1.w + w2 * v2.w + w3 * v3.w;
        }
        for (; e < n; e++) {
            int s0 = s_src[e];
            float w0 = s_w[e];
            float4 v0 = __ldcg((const float4*)(h + (size_t)s0 * FD) + t);
            acc.x += w0 * v0.x; acc.y += w0 * v0.y;
            acc.z += w0 * v0.z; acc.w += w0 * v0.w;
        }
        __syncthreads();
    }

    float4 b = *(const float4*)(bias + t * 4);
    acc.x = fmaxf(acc.x + b.x, 0.f);
    acc.y = fmaxf(acc.y + b.y, 0.f);
    acc.z = fmaxf(acc.z + b.z, 0.f);
    acc.w = fmaxf(acc.w + b.w, 0.f);

    size_t o = (size_t)node * FD + t * 4;
    if (SPLIT) {
        uint2 hi, lo;
        split4(acc, hi, lo);
        *(uint2*)(g_Ahi + o) = hi;
        *(uint2*)(g_Alo + o) = lo;
    } else {
        *(float4*)(g_bufB + o) = acc;
    }
}

// ----------------------------------------------------------------------------
// Final linear: out[N x 16] = g_bufB @ Wl + bl
// ----------------------------------------------------------------------------
__global__ __launch_bounds__(256)
void linear16_kernel(const float* __restrict__ W, const float* __restrict__ b,
                     float* __restrict__ out) {
    const float* h = (const float*)g_bufB;
    __shared__ float sW[FD * OUTD];
    int t = threadIdx.x;
    for (int i = t; i < FD * OUTD; i += 256) sW[i] = W[i];
    __syncthreads();

    int r = t >> 4;
    int c = t & 15;
    int row = blockIdx.x * 16 + r;
    if (row >= NN) return;

    const float4* hp = (const float4*)(h + (size_t)row * FD);
    float acc = 0.f;
#pragma unroll 4
    for (int k = 0; k < FD / 4; k++) {
        float4 v = hp[k];
        acc += v.x * sW[(4 * k + 0) * OUTD + c];
        acc += v.y * sW[(4 * k + 1) * OUTD + c];
        acc += v.z * sW[(4 * k + 2) * OUTD + c];
        acc += v.w * sW[(4 * k + 3) * OUTD + c];
    }
    out[(size_t)row * OUTD + c] = acc + b[c];
}

// ----------------------------------------------------------------------------
// Side stream + events for fork/join overlap (created once at static init).
// ----------------------------------------------------------------------------
namespace {
struct Aux {
    cudaStream_t s2 = nullptr;
    cudaEvent_t  eFork = nullptr, eJoin = nullptr;
    bool ok = false;
    Aux() {
        if (cudaStreamCreateWithFlags(&s2, cudaStreamNonBlocking) != cudaSuccess)
            return;
        if (cudaEventCreateWithFlags(&eFork, cudaEventDisableTiming) != cudaSuccess)
            return;
        if (cudaEventCreateWithFlags(&eJoin, cudaEventDisableTiming) != cudaSuccess)
            return;
        ok = true;
    }
};
Aux g_aux;
}

// ----------------------------------------------------------------------------
// Launch
// ----------------------------------------------------------------------------
extern "C" void kernel_launch(void* const* d_in, const int* in_sizes, int n_in,
                              void* d_out, int out_size) {
    const float* x  = (const float*)d_in[0];
    const int*   ei = (const int*)d_in[1];
    const float* W1 = (const float*)d_in[2];
    const float* b1 = (const float*)d_in[3];
    const float* W2 = (const float*)d_in[4];
    const float* b2 = (const float*)d_in[5];
    const float* Wl = (const float*)d_in[6];
    const float* bl = (const float*)d_in[7];
    float* out = (float*)d_out;

    cudaFuncSetAttribute(gemm_mma_kernel<0>,
                         cudaFuncAttributeMaxDynamicSharedMemorySize, GEMM_SMEM);
    cudaFuncSetAttribute(gemm_mma_kernel<1>,
                         cudaFuncAttributeMaxDynamicSharedMemorySize, GEMM_SMEM);

    dim3 gemmGrid(FD / 128, MTILES);                      // (4, 71) = 284 CTAs
    int convBlocks = (CONVA_ITEMS + CONVW_ITEMS + 255) / 256;

    if (g_aux.ok) {
        // Fork: CSR preprocessing on side stream, conversions + GEMM-0 on main.
        cudaEventRecord(g_aux.eFork, 0);
        cudaStreamWaitEvent(g_aux.s2, g_aux.eFork, 0);
        zero_counts_kernel<<<(NN + 255) / 256, 256, 0, g_aux.s2>>>();
        count_kernel<<<(NE + 255) / 256, 256, 0, g_aux.s2>>>(ei);
        scan_kernel<<<1, 1024, 0, g_aux.s2>>>();
        fill_kernel<<<(NE + 255) / 256, 256, 0, g_aux.s2>>>(ei);
        cudaEventRecord(g_aux.eJoin, g_aux.s2);

        conv_kernel<<<convBlocks, 256>>>(x, W1, W2);
        gemm_mma_kernel<0><<<gemmGrid, 384, GEMM_SMEM>>>();

        cudaStreamWaitEvent(0, g_aux.eJoin, 0);           // join before agg
    } else {
        // Serial fallback
        zero_counts_kernel<<<(NN + 255) / 256, 256>>>();
        count_kernel<<<(NE + 255) / 256, 256>>>(ei);
        scan_kernel<<<1, 1024>>>();
        fill_kernel<<<(NE + 255) / 256, 256>>>(ei);
        conv_kernel<<<convBlocks, 256>>>(x, W1, W2);
        gemm_mma_kernel<0><<<gemmGrid, 384, GEMM_SMEM>>>();
    }

    // Layer 1 aggregation -> bf16 split input of layer 2
    agg_kernel<true><<<NN, 128>>>(b1);

    // Layer 2
    gemm_mma_kernel<1><<<gemmGrid, 384, GEMM_SMEM>>>();
    agg_kernel<false><<<NN, 128>>>(b2);

    // Head
    linear16_kernel<<<(NN + 15) / 16, 256>>>(Wl, bl, out);
}